// round 10
// baseline (speedup 1.0000x reference)
#include <cuda_runtime.h>
#include <math.h>

// WassersteinLog via the similarity identity:
//   X = sqrt(A W + eps I),  A = cov1 + eps I, W = cov2
//   covv = X + X^T - 2 cov1 ;  miuv = miu2 - miu1
// sqrt(M) = c0 I + c1 M + c2 M^2 from eigenvalues (trig cubic) + divided differences.
// Persistent blocks: miu path first (overlaps cov staging), then chunk loop over cov.

namespace {

constexpr float EPSF = 1e-8f;
constexpr int TPB = 256;
constexpr int CHUNK4 = (TPB * 9) / 4;   // 576 float4 per cov chunk
constexpr int NBLOCKS = 148 * 8;        // one full resident wave on GB300 (148 SM x 8 blk)

__device__ __forceinline__ float fsqrt_fast(float x) {
    return x * rsqrtf(fmaxf(x, 1e-30f));
}

__device__ __forceinline__ float facos_fast(float r) {
    // Abramowitz-Stegun 4.4.45, abs err ~6.8e-5 rad, branchless sign handling.
    float ar = fabsf(r);
    float t  = fsqrt_fast(1.0f - ar);
    float p  = fmaf(fmaf(fmaf(-0.0187293f, ar, 0.0742610f), ar, -0.2121144f), ar, 1.5707288f);
    float a  = t * p;
    return (r >= 0.0f) ? a : (3.14159265358979f - a);
}

__global__ void __launch_bounds__(TPB, 8)
wlog_kernel(const float* __restrict__ miu1,
            const float* __restrict__ miu2,
            const float* __restrict__ cov1,
            const float* __restrict__ cov2,
            float* __restrict__ out_miu,
            float* __restrict__ out_cov,
            int B) {
    __shared__ float s1[TPB * 9];
    __shared__ float s2[TPB * 9];

    const int tid  = threadIdx.x;
    const int gtid = blockIdx.x * TPB + tid;
    const int gstride = gridDim.x * TPB;

    // ---- miu velocity FIRST: loads issue before any cov work, stores are fire-and-forget
    {
        const int nFlat = 3 * B;
        const int n4 = nFlat >> 2;
        const float4* m1_4 = reinterpret_cast<const float4*>(miu1);
        const float4* m2_4 = reinterpret_cast<const float4*>(miu2);
        float4* om_4 = reinterpret_cast<float4*>(out_miu);
        for (int j = gtid; j < n4; j += gstride) {
            float4 a = m1_4[j];
            float4 c = m2_4[j];
            float4 o;
            o.x = c.x - a.x; o.y = c.y - a.y; o.z = c.z - a.z; o.w = c.w - a.w;
            om_4[j] = o;
        }
        for (int j = (n4 << 2) + gtid; j < nFlat; j += gstride) {
            out_miu[j] = miu2[j] - miu1[j];
        }
    }

    // ---- persistent loop over cov chunks ----
    const int nChunks = (B + TPB - 1) / TPB;
    for (int c = blockIdx.x; c < nChunks; c += gridDim.x) {
        const int base  = c * TPB;
        const int nElem = min(TPB, B - base);

        // stage-in (coalesced float4 for full chunks)
        if (nElem == TPB) {
            const float4* g1 = reinterpret_cast<const float4*>(cov1 + (size_t)base * 9);
            const float4* g2 = reinterpret_cast<const float4*>(cov2 + (size_t)base * 9);
            float4* a1 = reinterpret_cast<float4*>(s1);
            float4* a2 = reinterpret_cast<float4*>(s2);
            #pragma unroll
            for (int i = tid; i < CHUNK4; i += TPB) {
                a1[i] = g1[i];
                a2[i] = g2[i];
            }
        } else {
            for (int i = tid; i < nElem * 9; i += TPB) {
                s1[i] = cov1[(size_t)base * 9 + i];
                s2[i] = cov2[(size_t)base * 9 + i];
            }
        }
        __syncthreads();

        if (tid < nElem) {
            const float* v1 = s1 + 9 * tid;
            const float* v2 = s2 + 9 * tid;
            float A00 = v1[0] + EPSF, A01 = v1[1], A02 = v1[2];
            float A11 = v1[4] + EPSF, A12 = v1[5], A22 = v1[8];
            float W00 = v2[0], W01 = v2[1], W02 = v2[2];
            float W11 = v2[4], W12 = v2[5], W22 = v2[8];

            // M = A * W + eps I
            float M00 = A00 * W00 + A01 * W01 + A02 * W02 + EPSF;
            float M01 = A00 * W01 + A01 * W11 + A02 * W12;
            float M02 = A00 * W02 + A01 * W12 + A02 * W22;
            float M10 = A01 * W00 + A11 * W01 + A12 * W02;
            float M11 = A01 * W01 + A11 * W11 + A12 * W12 + EPSF;
            float M12 = A01 * W02 + A11 * W12 + A12 * W22;
            float M20 = A02 * W00 + A12 * W01 + A22 * W02;
            float M21 = A02 * W01 + A12 * W11 + A22 * W12;
            float M22 = A02 * W02 + A12 * W12 + A22 * W22 + EPSF;

            // cancellation-free det(M) = det(A) det(W)
            float detA = A00 * (A11 * A22 - A12 * A12)
                       - A01 * (A01 * A22 - A12 * A02)
                       + A02 * (A01 * A12 - A11 * A02);
            float detW = W00 * (W11 * W22 - W12 * W12)
                       - W01 * (W01 * W22 - W12 * W02)
                       + W02 * (W01 * W12 - W11 * W02);
            float detM = detA * detW;

            // eigenvalues of M via trig cubic
            const float third = 1.0f / 3.0f;
            float q = (M00 + M11 + M22) * third;
            float B00 = M00 - q, B11 = M11 - q, B22 = M22 - q;
            float p2 = B00 * B00 + B11 * B11 + B22 * B22
                     + 2.0f * (M01 * M10 + M02 * M20 + M12 * M21);
            p2 = fmaxf(p2, 0.0f);
            float l1, l2, l3;
            if (p2 < 1e-24f) {
                l1 = l2 = l3 = q;
            } else {
                float t   = p2 * (1.0f / 6.0f);
                float irt = rsqrtf(t);
                float p   = t * irt;
                float detB = B00 * (B11 * B22 - M12 * M21)
                           - M01 * (M10 * B22 - M12 * M20)
                           + M02 * (M10 * M21 - B11 * M20);
                float r = 0.5f * (((detB * irt) * irt) * irt);
                r = fminf(1.0f, fmaxf(-1.0f, r));
                float phi = facos_fast(r) * third;
                float tp  = 2.0f * p;
                l1 = q + tp * __cosf(phi);
                l3 = q + tp * __cosf(phi + 2.0943951023931953f);  // +2*pi/3
                l2 = 3.0f * q - l1 - l3;
            }
            if (l3 < 0.05f * l1) {
                float pl = l1 * l2;
                if (pl > 1e-30f) l3 = fmaxf(__fdividef(detM, pl), 0.0f);
            }

            // divided-difference coefficients of sqrt
            float sq1 = fsqrt_fast(fabsf(l1));
            float sq2 = fsqrt_fast(fabsf(l2));
            float sq3 = fsqrt_fast(fabsf(l3));
            const float g = 1e-20f;
            float d12 = __fdividef(1.0f, sq1 + sq2 + g);
            float d13 = __fdividef(1.0f, sq1 + sq3 + g);
            float d23 = __fdividef(1.0f, sq2 + sq3 + g);
            float c2 = -(d12 * d13 * d23);
            float c1 = d12 - c2 * (l1 + l2);
            float c0 = sq1 - d12 * l1 + c2 * (l1 * l2);

            // M^2
            float P00 = M00 * M00 + M01 * M10 + M02 * M20;
            float P01 = M00 * M01 + M01 * M11 + M02 * M21;
            float P02 = M00 * M02 + M01 * M12 + M02 * M22;
            float P10 = M10 * M00 + M11 * M10 + M12 * M20;
            float P11 = M10 * M01 + M11 * M11 + M12 * M21;
            float P12 = M10 * M02 + M11 * M12 + M12 * M22;
            float P20 = M20 * M00 + M21 * M10 + M22 * M20;
            float P21 = M20 * M01 + M21 * M11 + M22 * M21;
            float P22 = M20 * M02 + M21 * M12 + M22 * M22;

            // covv = X + X^T - 2 cov1
            float O00 = 2.0f * (c0 + c1 * M00 + c2 * P00 - v1[0]);
            float O11 = 2.0f * (c0 + c1 * M11 + c2 * P11 - v1[4]);
            float O22 = 2.0f * (c0 + c1 * M22 + c2 * P22 - v1[8]);
            float O01 = c1 * (M01 + M10) + c2 * (P01 + P10) - 2.0f * v1[1];
            float O02 = c1 * (M02 + M20) + c2 * (P02 + P20) - 2.0f * v1[2];
            float O12 = c1 * (M12 + M21) + c2 * (P12 + P21) - 2.0f * v1[5];

            float* oc = s1 + 9 * tid;
            oc[0] = O00; oc[1] = O01; oc[2] = O02;
            oc[3] = O01; oc[4] = O11; oc[5] = O12;
            oc[6] = O02; oc[7] = O12; oc[8] = O22;
        }
        __syncthreads();

        // stage-out (coalesced)
        if (nElem == TPB) {
            float4* go = reinterpret_cast<float4*>(out_cov + (size_t)base * 9);
            const float4* a1 = reinterpret_cast<const float4*>(s1);
            #pragma unroll
            for (int i = tid; i < CHUNK4; i += TPB) {
                go[i] = a1[i];
            }
        } else {
            for (int i = tid; i < nElem * 9; i += TPB) {
                out_cov[(size_t)base * 9 + i] = s1[i];
            }
        }
        __syncthreads();   // guard smem reuse on next iteration
    }
}

}  // namespace

extern "C" void kernel_launch(void* const* d_in, const int* in_sizes, int n_in,
                              void* d_out, int out_size) {
    const float* miu1 = (const float*)d_in[0];
    const float* miu2 = (const float*)d_in[1];
    const float* cov1 = (const float*)d_in[2];
    const float* cov2 = (const float*)d_in[3];
    float* out = (float*)d_out;

    int B = in_sizes[0] / 3;
    float* out_miu = out;
    float* out_cov = out + (size_t)3 * B;

    int nChunks = (B + TPB - 1) / TPB;
    int blocks = NBLOCKS < nChunks ? NBLOCKS : nChunks;
    wlog_kernel<<<blocks, TPB>>>(miu1, miu2, cov1, cov2, out_miu, out_cov, B);
}

// round 13
// speedup vs baseline: 1.1488x; 1.1488x over previous
#include <cuda_runtime.h>
#include <math.h>

// WassersteinLog via the similarity identity:
//   X = sqrt(A W + eps I),  A = cov1 + eps I, W = cov2
//   covv = X + X^T - 2 cov1 ;  miuv = miu2 - miu1
// sqrt(M) = c0 I + c1 M + c2 M^2 from eigenvalues (trig cubic) + divided differences.
// Warp-autonomous tiles: each warp stages+computes+stores 32 elements with only
// __syncwarp() — no block barriers, no cross-warp coupling.

namespace {

constexpr float EPSF = 1e-8f;
constexpr int TPB = 256;
constexpr int WPB = TPB / 32;            // 8 warps per block
constexpr int EPW = 32;                  // elements per warp
constexpr int WCHUNK4 = EPW * 9 / 4;     // 72 float4 per warp tile

__device__ __forceinline__ float fsqrt_fast(float x) {
    return x * rsqrtf(fmaxf(x, 1e-30f));
}

__device__ __forceinline__ float facos_fast(float r) {
    // Abramowitz-Stegun 4.4.45, abs err ~6.8e-5 rad, branchless sign handling.
    float ar = fabsf(r);
    float t  = fsqrt_fast(1.0f - ar);
    float p  = fmaf(fmaf(fmaf(-0.0187293f, ar, 0.0742610f), ar, -0.2121144f), ar, 1.5707288f);
    float a  = t * p;
    return (r >= 0.0f) ? a : (3.14159265358979f - a);
}

__global__ void __launch_bounds__(TPB, 8)
wlog_kernel(const float* __restrict__ miu1,
            const float* __restrict__ miu2,
            const float* __restrict__ cov1,
            const float* __restrict__ cov2,
            float* __restrict__ out_miu,
            float* __restrict__ out_cov,
            int B) {
    __shared__ float sa[WPB][EPW * 9];   // cov1 tile per warp (reused for output)
    __shared__ float sb[WPB][EPW * 9];   // cov2 tile per warp

    const int tid  = threadIdx.x;
    const int wid  = tid >> 5;
    const int lane = tid & 31;
    const int gtid = blockIdx.x * TPB + tid;
    const int gstride = gridDim.x * TPB;

    // ---- miu velocity first: loads issue before cov staging, fire-and-forget
    {
        const int nFlat = 3 * B;
        const int n4 = nFlat >> 2;
        const float4* m1_4 = reinterpret_cast<const float4*>(miu1);
        const float4* m2_4 = reinterpret_cast<const float4*>(miu2);
        float4* om_4 = reinterpret_cast<float4*>(out_miu);
        for (int j = gtid; j < n4; j += gstride) {
            float4 a = m1_4[j];
            float4 c = m2_4[j];
            float4 o;
            o.x = c.x - a.x; o.y = c.y - a.y; o.z = c.z - a.z; o.w = c.w - a.w;
            om_4[j] = o;
        }
        for (int j = (n4 << 2) + gtid; j < nFlat; j += gstride) {
            out_miu[j] = miu2[j] - miu1[j];
        }
    }

    // ---- warp-autonomous cov tile ----
    const long long wbase = ((long long)blockIdx.x * WPB + wid) * EPW;
    if (wbase >= B) return;
    const int nE = (int)min((long long)EPW, (long long)B - wbase);

    float* s1 = sa[wid];
    float* s2 = sb[wid];

    // stage-in (coalesced float4 within the warp)
    if (nE == EPW) {
        const float4* g1 = reinterpret_cast<const float4*>(cov1 + (size_t)wbase * 9);
        const float4* g2 = reinterpret_cast<const float4*>(cov2 + (size_t)wbase * 9);
        float4* a1 = reinterpret_cast<float4*>(s1);
        float4* a2 = reinterpret_cast<float4*>(s2);
        #pragma unroll
        for (int i = lane; i < WCHUNK4; i += 32) {
            a1[i] = g1[i];
            a2[i] = g2[i];
        }
    } else {
        for (int i = lane; i < nE * 9; i += 32) {
            s1[i] = cov1[(size_t)wbase * 9 + i];
            s2[i] = cov2[(size_t)wbase * 9 + i];
        }
    }
    __syncwarp();

    if (lane < nE) {
        const float* v1 = s1 + 9 * lane;
        const float* v2 = s2 + 9 * lane;
        float A00 = v1[0] + EPSF, A01 = v1[1], A02 = v1[2];
        float A11 = v1[4] + EPSF, A12 = v1[5], A22 = v1[8];
        float W00 = v2[0], W01 = v2[1], W02 = v2[2];
        float W11 = v2[4], W12 = v2[5], W22 = v2[8];

        // M = A * W + eps I
        float M00 = A00 * W00 + A01 * W01 + A02 * W02 + EPSF;
        float M01 = A00 * W01 + A01 * W11 + A02 * W12;
        float M02 = A00 * W02 + A01 * W12 + A02 * W22;
        float M10 = A01 * W00 + A11 * W01 + A12 * W02;
        float M11 = A01 * W01 + A11 * W11 + A12 * W12 + EPSF;
        float M12 = A01 * W02 + A11 * W12 + A12 * W22;
        float M20 = A02 * W00 + A12 * W01 + A22 * W02;
        float M21 = A02 * W01 + A12 * W11 + A22 * W12;
        float M22 = A02 * W02 + A12 * W12 + A22 * W22 + EPSF;

        // cancellation-free det(M) = det(A) det(W)
        float detA = A00 * (A11 * A22 - A12 * A12)
                   - A01 * (A01 * A22 - A12 * A02)
                   + A02 * (A01 * A12 - A11 * A02);
        float detW = W00 * (W11 * W22 - W12 * W12)
                   - W01 * (W01 * W22 - W12 * W02)
                   + W02 * (W01 * W12 - W11 * W02);
        float detM = detA * detW;

        // eigenvalues of M via trig cubic
        const float third = 1.0f / 3.0f;
        float q = (M00 + M11 + M22) * third;
        float B00 = M00 - q, B11 = M11 - q, B22 = M22 - q;
        float p2 = B00 * B00 + B11 * B11 + B22 * B22
                 + 2.0f * (M01 * M10 + M02 * M20 + M12 * M21);
        p2 = fmaxf(p2, 0.0f);
        float l1, l2, l3;
        if (p2 < 1e-24f) {
            l1 = l2 = l3 = q;
        } else {
            float t   = p2 * (1.0f / 6.0f);
            float irt = rsqrtf(t);
            float p   = t * irt;
            float detB = B00 * (B11 * B22 - M12 * M21)
                       - M01 * (M10 * B22 - M12 * M20)
                       + M02 * (M10 * M21 - B11 * M20);
            float r = 0.5f * (((detB * irt) * irt) * irt);
            r = fminf(1.0f, fmaxf(-1.0f, r));
            float phi = facos_fast(r) * third;
            float tp  = 2.0f * p;
            l1 = q + tp * __cosf(phi);
            l3 = q + tp * __cosf(phi + 2.0943951023931953f);  // +2*pi/3
            l2 = 3.0f * q - l1 - l3;
        }
        if (l3 < 0.05f * l1) {
            float pl = l1 * l2;
            if (pl > 1e-30f) l3 = fmaxf(__fdividef(detM, pl), 0.0f);
        }

        // divided-difference coefficients of sqrt
        float sq1 = fsqrt_fast(fabsf(l1));
        float sq2 = fsqrt_fast(fabsf(l2));
        float sq3 = fsqrt_fast(fabsf(l3));
        const float g = 1e-20f;
        float d12 = __fdividef(1.0f, sq1 + sq2 + g);
        float d13 = __fdividef(1.0f, sq1 + sq3 + g);
        float d23 = __fdividef(1.0f, sq2 + sq3 + g);
        float c2 = -(d12 * d13 * d23);
        float c1 = d12 - c2 * (l1 + l2);
        float c0 = sq1 - d12 * l1 + c2 * (l1 * l2);

        // M^2
        float P00 = M00 * M00 + M01 * M10 + M02 * M20;
        float P01 = M00 * M01 + M01 * M11 + M02 * M21;
        float P02 = M00 * M02 + M01 * M12 + M02 * M22;
        float P10 = M10 * M00 + M11 * M10 + M12 * M20;
        float P11 = M10 * M01 + M11 * M11 + M12 * M21;
        float P12 = M10 * M02 + M11 * M12 + M12 * M22;
        float P20 = M20 * M00 + M21 * M10 + M22 * M20;
        float P21 = M20 * M01 + M21 * M11 + M22 * M21;
        float P22 = M20 * M02 + M21 * M12 + M22 * M22;

        // covv = X + X^T - 2 cov1
        float O00 = 2.0f * (c0 + c1 * M00 + c2 * P00 - v1[0]);
        float O11 = 2.0f * (c0 + c1 * M11 + c2 * P11 - v1[4]);
        float O22 = 2.0f * (c0 + c1 * M22 + c2 * P22 - v1[8]);
        float O01 = c1 * (M01 + M10) + c2 * (P01 + P10) - 2.0f * v1[1];
        float O02 = c1 * (M02 + M20) + c2 * (P02 + P20) - 2.0f * v1[2];
        float O12 = c1 * (M12 + M21) + c2 * (P12 + P21) - 2.0f * v1[5];

        float* oc = s1 + 9 * lane;   // lane-private slot, reuse cov1 tile
        oc[0] = O00; oc[1] = O01; oc[2] = O02;
        oc[3] = O01; oc[4] = O11; oc[5] = O12;
        oc[6] = O02; oc[7] = O12; oc[8] = O22;
    }
    __syncwarp();

    // stage-out (coalesced float4 within the warp)
    if (nE == EPW) {
        float4* go = reinterpret_cast<float4*>(out_cov + (size_t)wbase * 9);
        const float4* a1 = reinterpret_cast<const float4*>(s1);
        #pragma unroll
        for (int i = lane; i < WCHUNK4; i += 32) {
            go[i] = a1[i];
        }
    } else {
        for (int i = lane; i < nE * 9; i += 32) {
            out_cov[(size_t)wbase * 9 + i] = s1[i];
        }
    }
}

}  // namespace

extern "C" void kernel_launch(void* const* d_in, const int* in_sizes, int n_in,
                              void* d_out, int out_size) {
    const float* miu1 = (const float*)d_in[0];
    const float* miu2 = (const float*)d_in[1];
    const float* cov1 = (const float*)d_in[2];
    const float* cov2 = (const float*)d_in[3];
    float* out = (float*)d_out;

    int B = in_sizes[0] / 3;
    float* out_miu = out;
    float* out_cov = out + (size_t)3 * B;

    int elemsPerBlock = WPB * EPW;   // 256
    int blocks = (B + elemsPerBlock - 1) / elemsPerBlock;
    wlog_kernel<<<blocks, TPB>>>(miu1, miu2, cov1, cov2, out_miu, out_cov, B);
}